// round 8
// baseline (speedup 1.0000x reference)
#include <cuda_runtime.h>

#define NB 32
#define CI 64
#define LT 300
#define V  25
#define VP 26
#define KD 192

typedef unsigned long long ull;

// scratch: xwin[n][m][c][26]; v=25 pad column never written -> stays 0 (zero-init)
__device__ float g_xwin[(size_t)NB * LT * CI * VP];

__device__ __forceinline__ ull pack2(float lo, float hi){
    ull r; asm("mov.b64 %0,{%1,%2};" : "=l"(r) : "f"(lo), "f"(hi)); return r;
}
__device__ __forceinline__ void unpack2(ull v, float& lo, float& hi){
    asm("mov.b64 {%0,%1},%2;" : "=f"(lo), "=f"(hi) : "l"(v));
}
__device__ __forceinline__ ull ffma2(ull a, ull b, ull c){
    ull d; asm("fma.rn.f32x2 %0,%1,%2,%3;" : "=l"(d) : "l"(a), "l"(b), "l"(c)); return d;
}
__device__ __forceinline__ unsigned smem_u32(const void* p){
    unsigned a;
    asm("{ .reg .u64 t; cvta.to.shared.u64 t, %1; cvt.u32.u64 %0, t; }" : "=r"(a) : "l"(p));
    return a;
}

// ---------- kernel 1: 9-tap causal window sum, register running-sum stream ----------
#define WCG 8
#define WLQ 75
#define WTH (WCG * V)

__global__ __launch_bounds__(WTH) void win_kernel(const float* __restrict__ x){
    const int b  = blockIdx.x;
    const int q  = b & 3;
    const int cg = (b >> 2) & 7;
    const int n  = b >> 5;
    const int t  = threadIdx.x;
    const int cl = t / V;
    const int v  = t - cl * V;
    const int c  = cg * WCG + cl;
    const int l0 = q * WLQ;

    const float* xp = x + ((size_t)(n * CI + c) * LT) * V + v;
    float* op = g_xwin + ((size_t)n * LT * CI + c) * VP + v;

    float ring[9];
    #pragma unroll
    for (int j = 0; j < 9; j++) ring[j] = 0.f;
    float s = 0.f;

    #pragma unroll 1
    for (int base = 0; base < 90; base += 9) {
        #pragma unroll
        for (int j = 0; j < 9; j++) {
            int l = l0 - 8 + base + j;
            float nv = (l >= 0 && l < LT) ? xp[(size_t)l * V] : 0.f;
            s += nv - ring[j];
            ring[j] = nv;
            if (l >= l0 && l < l0 + WLQ)
                op[(size_t)l * CI * VP] = s;
        }
    }
}

// ---------- kernel 2: persistent fused contraction + BN + ReLU + residual ----------
// grid = 32n x 10 chunks; each block: 30 m = 15 iters of MT=2.
// TPB=288, 2 blocks/SM (18 warps/SM). W staged to smem ONCE per block.
// xwf for next m-pair prefetched via cp.async during phase 2.
#define TPB 288
#define MCHUNK 10          // chunks per n
#define MITER 15           // iterations per block (MT=2 each)
// Wsm 49152 + As 9600 + xwf 13312 + ysm 39936 + bn 512 = 112512 B
#define MAIN_SMEM (CI*KD*4 + 75*16*8 + 2*CI*VP*4 + 2*KD*VP*4 + 2*CI*4)

__global__ __launch_bounds__(TPB, 2) void main_kernel(
    const float* __restrict__ x,
    const float* __restrict__ A,
    const float* __restrict__ W,
    const float* __restrict__ gamma,
    const float* __restrict__ beta,
    const float* __restrict__ mean,
    const float* __restrict__ var,
    float* __restrict__ out)
{
    extern __shared__ float smemf[];
    float* Wsm = smemf;                          // [64][192]
    ull*   As  = (ull*)(smemf + CI*KD);          // [75][16] packed w-pairs (13..15 zero)
    float* xwf = (float*)(As + 75*16);           // [2][64][26]
    float* ysm = xwf + 2*CI*VP;                  // [2][192][26]
    float* bnA = ysm + 2*KD*VP;                  // [64]
    float* bnB = bnA + CI;                       // [64]

    const int tid = threadIdx.x;
    const int n     = blockIdx.x / MCHUNK;
    const int mbase = (blockIdx.x % MCHUNK) * (2 * MITER);

    const unsigned wb  = smem_u32(Wsm);
    const unsigned xwb = smem_u32(xwf);

    // ---- one-time staging: W (48 KB) + first xwf tile via cp.async ----
    {
        const char* ws = (const char*)W;
        #pragma unroll
        for (int j = 0; j < 11; j++){
            int idx = j*TPB + tid;
            if (idx < (CI*KD*4)/16)
                asm volatile("cp.async.cg.shared.global [%0], [%1], 16;"
                             :: "r"(wb + (unsigned)(idx*16)), "l"(ws + (size_t)idx*16));
        }
        const char* xs = (const char*)(g_xwin + (size_t)(n*LT + mbase)*CI*VP);
        #pragma unroll
        for (int j = 0; j < 3; j++){
            int idx = j*TPB + tid;
            if (idx < (2*CI*VP*4)/16)
                asm volatile("cp.async.cg.shared.global [%0], [%1], 16;"
                             :: "r"(xwb + (unsigned)(idx*16)), "l"(xs + (size_t)idx*16));
        }
        asm volatile("cp.async.commit_group;");
    }

    if (tid < CI){
        float inv = gamma[tid] * rsqrtf(var[tid] + 1e-3f);
        bnA[tid] = inv;
        bnB[tid] = beta[tid] - mean[tid]*inv;
    }
    for (int i = tid; i < 75*16; i += TPB){
        int pv = i >> 4, wp = i & 15;
        ull val = 0;
        if (wp < 13){
            float a0 = A[pv*V + 2*wp];
            float a1 = (wp < 12) ? A[pv*V + 2*wp + 1] : 0.f;
            val = pack2(a0, a1);
        }
        As[i] = val;
    }
    asm volatile("cp.async.wait_group 0;");
    __syncthreads();

    // thread mappings (loop-invariant)
    const int p1_mslot = tid / 144;
    const int p1_s     = tid - p1_mslot*144;
    const int p1_kg    = p1_s / 3;            // 0..47, k-tile 4
    const int p1_vq    = p1_s - p1_kg*3;      // 0..2, vp offsets {0,4,8}, 5 pairs each
    const int p1_k0    = p1_kg * 4;
    const int p1_voff  = p1_vq * 4;

    #pragma unroll 1
    for (int it = 0; it < MITER; it++){
        const int m0 = mbase + 2*it;

        // ---- phase 1: y[k,:] = sum_c xw[c,:]*W[c,k]; 4 k-rows x 5 v-pairs ----
        // pairs 4 and 8 duplicated across vq groups (identical values) -> benign
        {
            const ull* xr = (const ull*)(xwf + p1_mslot*CI*VP) + p1_voff;
            const float* wr = Wsm + p1_k0;

            ull acc[4][5];
            #pragma unroll
            for (int i = 0; i < 4; i++)
                #pragma unroll
                for (int vp = 0; vp < 5; vp++) acc[i][vp] = 0;

            #pragma unroll 4
            for (int c = 0; c < CI; c++){
                float4 wa = *(const float4*)(wr + c*KD);
                ull w0 = pack2(wa.x, wa.x), w1 = pack2(wa.y, wa.y);
                ull w2 = pack2(wa.z, wa.z), w3 = pack2(wa.w, wa.w);
                const ull* xc = xr + c*13;
                ull xv0 = xc[0], xv1 = xc[1], xv2 = xc[2], xv3 = xc[3], xv4 = xc[4];
                acc[0][0]=ffma2(w0,xv0,acc[0][0]); acc[0][1]=ffma2(w0,xv1,acc[0][1]);
                acc[0][2]=ffma2(w0,xv2,acc[0][2]); acc[0][3]=ffma2(w0,xv3,acc[0][3]);
                acc[0][4]=ffma2(w0,xv4,acc[0][4]);
                acc[1][0]=ffma2(w1,xv0,acc[1][0]); acc[1][1]=ffma2(w1,xv1,acc[1][1]);
                acc[1][2]=ffma2(w1,xv2,acc[1][2]); acc[1][3]=ffma2(w1,xv3,acc[1][3]);
                acc[1][4]=ffma2(w1,xv4,acc[1][4]);
                acc[2][0]=ffma2(w2,xv0,acc[2][0]); acc[2][1]=ffma2(w2,xv1,acc[2][1]);
                acc[2][2]=ffma2(w2,xv2,acc[2][2]); acc[2][3]=ffma2(w2,xv3,acc[2][3]);
                acc[2][4]=ffma2(w2,xv4,acc[2][4]);
                acc[3][0]=ffma2(w3,xv0,acc[3][0]); acc[3][1]=ffma2(w3,xv1,acc[3][1]);
                acc[3][2]=ffma2(w3,xv2,acc[3][2]); acc[3][3]=ffma2(w3,xv3,acc[3][3]);
                acc[3][4]=ffma2(w3,xv4,acc[3][4]);
            }
            #pragma unroll
            for (int i = 0; i < 4; i++){
                ull* yr = (ull*)(ysm) + (size_t)(p1_mslot*KD + p1_k0 + i)*13 + p1_voff;
                #pragma unroll
                for (int vp = 0; vp < 5; vp++) yr[vp] = acc[i][vp];
            }
        }
        __syncthreads();

        // ---- prefetch next m-pair's xwin tile (phase 2 never reads xwf) ----
        if (it + 1 < MITER){
            const char* xs = (const char*)(g_xwin + (size_t)(n*LT + m0 + 2)*CI*VP);
            #pragma unroll
            for (int j = 0; j < 3; j++){
                int idx = j*TPB + tid;
                if (idx < (2*CI*VP*4)/16)
                    asm volatile("cp.async.cg.shared.global [%0], [%1], 16;"
                                 :: "r"(xwb + (unsigned)(idx*16)), "l"(xs + (size_t)idx*16));
            }
        }
        asm volatile("cp.async.commit_group;");

        // ---- phase 2: t[co,w] = sum_{p,v} y[co*3+p,v]*A[p,v,w]; 4co x 4wp ----
        if (tid < 256){
            const int mslot = tid >> 7;
            const int s2    = tid & 127;
            const int cog   = s2 >> 3;       // wait: need 4co x 4wg = 64 slots/m
            // remap: s2 in [0,128): use only s2<64 per mslot? No -> use 2co tile.
            const int cog2  = s2 >> 2;       // 32 groups of 2 co
            const int wg    = s2 & 3;
            const int co0   = cog2 * 2;
            (void)cog;

            ull tac[2][4];
            #pragma unroll
            for (int i = 0; i < 2; i++)
                #pragma unroll
                for (int j = 0; j < 4; j++) tac[i][j] = 0;

            const float* yb = ysm + (size_t)mslot*KD*VP;
            #pragma unroll
            for (int p = 0; p < 3; p++){
                const ull* Ab = As + (p*V)*16 + wg*4;
                const float* yp = yb + (size_t)(co0*3 + p)*VP;
                #pragma unroll 3
                for (int v2 = 0; v2 < 12; v2++){
                    int v = 2*v2;
                    ulonglong2 aA0 = *(const ulonglong2*)(Ab + (v  )*16);
                    ulonglong2 aB0 = *(const ulonglong2*)(Ab + (v  )*16 + 2);
                    ulonglong2 aA1 = *(const ulonglong2*)(Ab + (v+1)*16);
                    ulonglong2 aB1 = *(const ulonglong2*)(Ab + (v+1)*16 + 2);
                    #pragma unroll
                    for (int i = 0; i < 2; i++){
                        float y0, y1;
                        unpack2(*(const ull*)(yp + i*3*VP + v), y0, y1);
                        ull yy0 = pack2(y0, y0), yy1 = pack2(y1, y1);
                        tac[i][0] = ffma2(yy0, aA0.x, tac[i][0]);
                        tac[i][1] = ffma2(yy0, aA0.y, tac[i][1]);
                        tac[i][2] = ffma2(yy0, aB0.x, tac[i][2]);
                        tac[i][3] = ffma2(yy0, aB0.y, tac[i][3]);
                        tac[i][0] = ffma2(yy1, aA1.x, tac[i][0]);
                        tac[i][1] = ffma2(yy1, aA1.y, tac[i][1]);
                        tac[i][2] = ffma2(yy1, aB1.x, tac[i][2]);
                        tac[i][3] = ffma2(yy1, aB1.y, tac[i][3]);
                    }
                }
                { // leftover v = 24
                    ulonglong2 aA = *(const ulonglong2*)(Ab + 24*16);
                    ulonglong2 aB = *(const ulonglong2*)(Ab + 24*16 + 2);
                    #pragma unroll
                    for (int i = 0; i < 2; i++){
                        float yv = yp[i*3*VP + 24];
                        ull yy = pack2(yv, yv);
                        tac[i][0] = ffma2(yy, aA.x, tac[i][0]);
                        tac[i][1] = ffma2(yy, aA.y, tac[i][1]);
                        tac[i][2] = ffma2(yy, aB.x, tac[i][2]);
                        tac[i][3] = ffma2(yy, aB.y, tac[i][3]);
                    }
                }
            }

            const int m = m0 + mslot;
            #pragma unroll
            for (int i = 0; i < 2; i++){
                int co = co0 + i;
                float iv = bnA[co], bb = bnB[co];
                size_t base = ((size_t)(n*CI + co)*LT + m)*V;
                #pragma unroll
                for (int j = 0; j < 4; j++){
                    int w0 = 2*(wg*4 + j);
                    if (w0 >= V) break;
                    float t0, t1; unpack2(tac[i][j], t0, t1);
                    float r0 = fmaxf(fmaf(t0, iv, bb), 0.f);
                    out[base + w0] = fmaxf(r0 + x[base + w0], 0.f);
                    if (w0 + 1 < V){
                        float r1 = fmaxf(fmaf(t1, iv, bb), 0.f);
                        out[base + w0 + 1] = fmaxf(r1 + x[base + w0 + 1], 0.f);
                    }
                }
            }
        }
        asm volatile("cp.async.wait_group 0;");
        __syncthreads();
    }
}

extern "C" void kernel_launch(void* const* d_in, const int* in_sizes, int n_in,
                              void* d_out, int out_size) {
    const float* x     = (const float*)d_in[0];
    const float* A     = (const float*)d_in[1];
    const float* W     = (const float*)d_in[2];
    const float* gamma = (const float*)d_in[3];
    const float* beta  = (const float*)d_in[4];
    const float* mean  = (const float*)d_in[5];
    const float* var   = (const float*)d_in[6];
    float* out = (float*)d_out;

    win_kernel<<<NB * 8 * 4, WTH>>>(x);

    cudaFuncSetAttribute(main_kernel, cudaFuncAttributeMaxDynamicSharedMemorySize, MAIN_SMEM);
    main_kernel<<<NB * MCHUNK, TPB, MAIN_SMEM>>>(x, A, W, gamma, beta, mean, var, out);
}

// round 9
// speedup vs baseline: 1.4785x; 1.4785x over previous
#include <cuda_runtime.h>

#define NB 32
#define CI 64
#define LT 300
#define V  25
#define VP 26
#define KD 192

typedef unsigned long long ull;

// scratch: xwin[n][m][c][26]; v=25 pad column never written -> stays 0 (zero-init)
__device__ float g_xwin[(size_t)NB * LT * CI * VP];
// precomputed packed A [75][16] and BN constants [bnA(64), bnB(64)]
__device__ __align__(16) ull   g_As[75 * 16];
__device__ __align__(16) float g_bn[2 * CI];

__device__ __forceinline__ ull pack2(float lo, float hi){
    ull r; asm("mov.b64 %0,{%1,%2};" : "=l"(r) : "f"(lo), "f"(hi)); return r;
}
__device__ __forceinline__ void unpack2(ull v, float& lo, float& hi){
    asm("mov.b64 {%0,%1},%2;" : "=f"(lo), "=f"(hi) : "l"(v));
}
__device__ __forceinline__ ull ffma2(ull a, ull b, ull c){
    ull d; asm("fma.rn.f32x2 %0,%1,%2,%3;" : "=l"(d) : "l"(a), "l"(b), "l"(c)); return d;
}
__device__ __forceinline__ unsigned smem_u32(const void* p){
    unsigned a;
    asm("{ .reg .u64 t; cvta.to.shared.u64 t, %1; cvt.u32.u64 %0, t; }" : "=r"(a) : "l"(p));
    return a;
}

// ---------- kernel 1: 9-tap causal window sum + one-time setup (block 0) ----------
#define WCG 8
#define WLQ 75
#define WTH (WCG * V)

__global__ __launch_bounds__(WTH) void win_kernel(
    const float* __restrict__ x,
    const float* __restrict__ A,
    const float* __restrict__ gamma,
    const float* __restrict__ beta,
    const float* __restrict__ mean,
    const float* __restrict__ var)
{
    const int b  = blockIdx.x;
    const int t  = threadIdx.x;

    // block 0 additionally builds g_As and g_bn (tiny, overlapped with the grid)
    if (b == 0){
        if (t < CI){
            float inv = gamma[t] * rsqrtf(var[t] + 1e-3f);
            g_bn[t]      = inv;
            g_bn[CI + t] = beta[t] - mean[t]*inv;
        }
        for (int i = t; i < 75*16; i += WTH){
            int pv = i >> 4, wp = i & 15;
            ull val = 0;
            if (wp < 13){
                float a0 = A[pv*V + 2*wp];
                float a1 = (wp < 12) ? A[pv*V + 2*wp + 1] : 0.f;
                val = pack2(a0, a1);
            }
            g_As[i] = val;
        }
    }

    const int q  = b & 3;
    const int cg = (b >> 2) & 7;
    const int n  = b >> 5;
    const int cl = t / V;
    const int v  = t - cl * V;
    const int c  = cg * WCG + cl;
    const int l0 = q * WLQ;

    const float* xp = x + ((size_t)(n * CI + c) * LT) * V + v;
    float* op = g_xwin + ((size_t)n * LT * CI + c) * VP + v;

    float ring[9];
    #pragma unroll
    for (int j = 0; j < 9; j++) ring[j] = 0.f;
    float s = 0.f;

    #pragma unroll 1
    for (int base = 0; base < 90; base += 9) {
        #pragma unroll
        for (int j = 0; j < 9; j++) {
            int l = l0 - 8 + base + j;
            float nv = (l >= 0 && l < LT) ? xp[(size_t)l * V] : 0.f;
            s += nv - ring[j];
            ring[j] = nv;
            if (l >= l0 && l < l0 + WLQ)
                op[(size_t)l * CI * VP] = s;
        }
    }
}

// ---------- kernel 2: fused contraction + BN + ReLU + residual ----------
// TPB=192, one m-pair per block, 3 blocks/SM. All init via cp.async from
// precomputed globals; residual x staged to smem (epilogue LDS, no LDG stall).
#define TPB 192
// As 9600 | xwf 13312 | ysm 39936 | xres 12800 | bn 512  = 76160 B
#define OFF_XWF  (9600)
#define OFF_YSM  (OFF_XWF + 2*CI*VP*4)
#define OFF_XRES (OFF_YSM + 2*KD*VP*4)
#define OFF_BN   (OFF_XRES + 2*CI*V*4)
#define MAIN_SMEM (OFF_BN + 2*CI*4)

__global__ __launch_bounds__(TPB, 3) void main_kernel(
    const float* __restrict__ x,
    const float* __restrict__ W,
    float* __restrict__ out)
{
    extern __shared__ char smraw[];
    ull*   As   = (ull*)smraw;                       // [75][16]
    float* xwf  = (float*)(smraw + OFF_XWF);         // [2][64][26]
    float* ysm  = (float*)(smraw + OFF_YSM);         // [2][192][26]
    float* xres = (float*)(smraw + OFF_XRES);        // [64][2][25]
    float* bnA  = (float*)(smraw + OFF_BN);          // [64]
    float* bnB  = bnA + CI;                          // [64]

    const int tid = threadIdx.x;
    const int n   = blockIdx.x / (LT/2);
    const int m0  = (blockIdx.x % (LT/2)) * 2;

    // ---- init: pure cp.async staging (no ALU, no LDG round-trips) ----
    {
        const unsigned sb = smem_u32(smraw);
        // As: 600 x 16B
        const char* srcA = (const char*)g_As;
        #pragma unroll
        for (int j = 0; j < 4; j++){
            int idx = j*TPB + tid;
            if (idx < 600)
                asm volatile("cp.async.cg.shared.global [%0], [%1], 16;"
                             :: "r"(sb + (unsigned)(idx*16)), "l"(srcA + (size_t)idx*16));
        }
        // bn: 32 x 16B
        if (tid < 32){
            const char* srcB = (const char*)g_bn;
            asm volatile("cp.async.cg.shared.global [%0], [%1], 16;"
                         :: "r"(sb + OFF_BN + (unsigned)(tid*16)), "l"(srcB + (size_t)tid*16));
        }
        // xwf: 832 x 16B
        const char* srcX = (const char*)(g_xwin + (size_t)(n*LT + m0)*CI*VP);
        #pragma unroll
        for (int j = 0; j < 5; j++){
            int idx = j*TPB + tid;
            if (idx < 832)
                asm volatile("cp.async.cg.shared.global [%0], [%1], 16;"
                             :: "r"(sb + OFF_XWF + (unsigned)(idx*16)), "l"(srcX + (size_t)idx*16));
        }
        // xres: residual x tile, 64 rows x 50 floats = 1600 x 8B chunks, contiguous per row
        const char* srcR = (const char*)(x + ((size_t)(n*CI)*LT + m0)*V);
        #pragma unroll
        for (int j = 0; j < 9; j++){
            int idx = j*TPB + tid;
            if (idx < 1600){
                int c  = idx / 25;
                int jj = idx - c*25;
                asm volatile("cp.async.ca.shared.global [%0], [%1], 8;"
                             :: "r"(sb + OFF_XRES + (unsigned)(idx*8)),
                                "l"(srcR + (size_t)c*(LT*V*4) + (size_t)jj*8));
            }
        }
        asm volatile("cp.async.commit_group;");
        asm volatile("cp.async.wait_group 0;");
    }
    __syncthreads();

    // ---- phase 1: y[k,:] = sum_c xw[c,:]*W[c,k]; 4 k-rows x 7 v-pairs per thread ----
    // v-halves: vh0 -> pairs 0..6, vh1 -> pairs 6..12 (pair 6 duplicated, identical)
    {
        const int mslot = tid / 96;
        const int s     = tid - mslot*96;
        const int kg    = s >> 1;
        const int vh    = s & 1;
        const int k0    = kg * 4;
        const int voff  = vh * 6;
        const ull* xr = (const ull*)(xwf + mslot*CI*VP);

        ull acc[4][7];
        #pragma unroll
        for (int i = 0; i < 4; i++)
            #pragma unroll
            for (int vp = 0; vp < 7; vp++) acc[i][vp] = 0;

        #pragma unroll 2
        for (int c = 0; c < CI; c++){
            float4 w = __ldg((const float4*)(W + c*KD + k0));
            ull w0 = pack2(w.x, w.x), w1 = pack2(w.y, w.y);
            ull w2 = pack2(w.z, w.z), w3 = pack2(w.w, w.w);
            const ull* xc = xr + c*13 + voff;
            #pragma unroll
            for (int vp = 0; vp < 7; vp++){
                ull xv = xc[vp];
                acc[0][vp] = ffma2(w0, xv, acc[0][vp]);
                acc[1][vp] = ffma2(w1, xv, acc[1][vp]);
                acc[2][vp] = ffma2(w2, xv, acc[2][vp]);
                acc[3][vp] = ffma2(w3, xv, acc[3][vp]);
            }
        }
        #pragma unroll
        for (int i = 0; i < 4; i++){
            ull* yr = (ull*)(ysm) + (size_t)(mslot*KD + k0 + i)*13 + voff;
            #pragma unroll
            for (int vp = 0; vp < 7; vp++) yr[vp] = acc[i][vp];
        }
    }
    __syncthreads();

    // ---- phase 2: t[co,w] = sum_{p,v} y[co*3+p,v]*A[p,v,w]; 4co x 4wpairs ----
    if (tid < 128){
        const int mslot = tid >> 6;
        const int s2    = tid & 63;
        const int cog   = s2 >> 2;      // 16 groups of 4 co
        const int wg    = s2 & 3;
        const int co0   = cog * 4;

        ull tac[4][4];
        #pragma unroll
        for (int i = 0; i < 4; i++)
            #pragma unroll
            for (int j = 0; j < 4; j++) tac[i][j] = 0;

        const float* yb = ysm + (size_t)mslot*KD*VP;
        #pragma unroll
        for (int p = 0; p < 3; p++){
            const ull* Ab = As + (p*V)*16 + wg*4;
            const float* yp = yb + (size_t)(co0*3 + p)*VP;
            #pragma unroll 3
            for (int v2 = 0; v2 < 12; v2++){
                int v = 2*v2;
                ulonglong2 aA0 = *(const ulonglong2*)(Ab + (v  )*16);
                ulonglong2 aB0 = *(const ulonglong2*)(Ab + (v  )*16 + 2);
                ulonglong2 aA1 = *(const ulonglong2*)(Ab + (v+1)*16);
                ulonglong2 aB1 = *(const ulonglong2*)(Ab + (v+1)*16 + 2);
                #pragma unroll
                for (int i = 0; i < 4; i++){
                    float y0, y1;
                    unpack2(*(const ull*)(yp + i*3*VP + v), y0, y1);
                    ull yy0 = pack2(y0, y0), yy1 = pack2(y1, y1);
                    tac[i][0] = ffma2(yy0, aA0.x, tac[i][0]);
                    tac[i][1] = ffma2(yy0, aA0.y, tac[i][1]);
                    tac[i][2] = ffma2(yy0, aB0.x, tac[i][2]);
                    tac[i][3] = ffma2(yy0, aB0.y, tac[i][3]);
                    tac[i][0] = ffma2(yy1, aA1.x, tac[i][0]);
                    tac[i][1] = ffma2(yy1, aA1.y, tac[i][1]);
                    tac[i][2] = ffma2(yy1, aB1.x, tac[i][2]);
                    tac[i][3] = ffma2(yy1, aB1.y, tac[i][3]);
                }
            }
            { // leftover v = 24
                ulonglong2 aA = *(const ulonglong2*)(Ab + 24*16);
                ulonglong2 aB = *(const ulonglong2*)(Ab + 24*16 + 2);
                #pragma unroll
                for (int i = 0; i < 4; i++){
                    float yv = yp[i*3*VP + 24];
                    ull yy = pack2(yv, yv);
                    tac[i][0] = ffma2(yy, aA.x, tac[i][0]);
                    tac[i][1] = ffma2(yy, aA.y, tac[i][1]);
                    tac[i][2] = ffma2(yy, aB.x, tac[i][2]);
                    tac[i][3] = ffma2(yy, aB.y, tac[i][3]);
                }
            }
        }

        // epilogue: BN + ReLU + residual (from smem) + ReLU
        const int m = m0 + mslot;
        #pragma unroll
        for (int i = 0; i < 4; i++){
            int co = co0 + i;
            float iv = bnA[co], bb = bnB[co];
            const float* xr2 = xres + co*50 + mslot*25;
            size_t base = ((size_t)(n*CI + co)*LT + m)*V;
            #pragma unroll
            for (int j = 0; j < 4; j++){
                int w0 = 2*(wg*4 + j);
                if (w0 >= V) break;
                float t0, t1; unpack2(tac[i][j], t0, t1);
                float r0 = fmaxf(fmaf(t0, iv, bb), 0.f);
                out[base + w0] = fmaxf(r0 + xr2[w0], 0.f);
                if (w0 + 1 < V){
                    float r1 = fmaxf(fmaf(t1, iv, bb), 0.f);
                    out[base + w0 + 1] = fmaxf(r1 + xr2[w0 + 1], 0.f);
                }
            }
        }
    }
}

extern "C" void kernel_launch(void* const* d_in, const int* in_sizes, int n_in,
                              void* d_out, int out_size) {
    const float* x     = (const float*)d_in[0];
    const float* A     = (const float*)d_in[1];
    const float* W     = (const float*)d_in[2];
    const float* gamma = (const float*)d_in[3];
    const float* beta  = (const float*)d_in[4];
    const float* mean  = (const float*)d_in[5];
    const float* var   = (const float*)d_in[6];
    float* out = (float*)d_out;

    win_kernel<<<NB * 8 * 4, WTH>>>(x, A, gamma, beta, mean, var);

    cudaFuncSetAttribute(main_kernel, cudaFuncAttributeMaxDynamicSharedMemorySize, MAIN_SMEM);
    main_kernel<<<NB * (LT/2), TPB, MAIN_SMEM>>>(x, W, out);
}

// round 10
// speedup vs baseline: 1.5410x; 1.0422x over previous
#include <cuda_runtime.h>

#define NB 32
#define CI 64
#define LT 300
#define V  25
#define VP 26
#define KD 192

typedef unsigned long long ull;

// scratch: xwin[n][m][c][26]; v=25 pad column never written -> stays 0 (zero-init)
__device__ float g_xwin[(size_t)NB * LT * CI * VP];

__device__ __forceinline__ ull pack2(float lo, float hi){
    ull r; asm("mov.b64 %0,{%1,%2};" : "=l"(r) : "f"(lo), "f"(hi)); return r;
}
__device__ __forceinline__ void unpack2(ull v, float& lo, float& hi){
    asm("mov.b64 {%0,%1},%2;" : "=f"(lo), "=f"(hi) : "l"(v));
}
__device__ __forceinline__ ull ffma2(ull a, ull b, ull c){
    ull d; asm("fma.rn.f32x2 %0,%1,%2,%3;" : "=l"(d) : "l"(a), "l"(b), "l"(c)); return d;
}

// ---------- kernel 1: 9-tap causal window sum, register running-sum stream ----------
#define WCG 8
#define WLQ 75
#define WTH (WCG * V)

__global__ __launch_bounds__(WTH) void win_kernel(const float* __restrict__ x){
    const int b  = blockIdx.x;
    const int q  = b & 3;
    const int cg = (b >> 2) & 7;
    const int n  = b >> 5;
    const int t  = threadIdx.x;
    const int cl = t / V;
    const int v  = t - cl * V;
    const int c  = cg * WCG + cl;
    const int l0 = q * WLQ;

    const float* xp = x + ((size_t)(n * CI + c) * LT) * V + v;
    float* op = g_xwin + ((size_t)n * LT * CI + c) * VP + v;

    float ring[9];
    #pragma unroll
    for (int j = 0; j < 9; j++) ring[j] = 0.f;
    float s = 0.f;

    #pragma unroll 1
    for (int base = 0; base < 90; base += 9) {
        #pragma unroll
        for (int j = 0; j < 9; j++) {
            int l = l0 - 8 + base + j;
            float nv = (l >= 0 && l < LT) ? xp[(size_t)l * V] : 0.f;
            s += nv - ring[j];
            ring[j] = nv;
            if (l >= l0 && l < l0 + WLQ)
                op[(size_t)l * CI * VP] = s;
        }
    }
}

// ---------- kernel 2: fused contraction + BN + ReLU + residual ----------
// Identical to the best (R4) config except phase 1 software-pipelines the W
// loads 4 c-iterations deep (MLP=4) to bury the ~250-cyc L2 scoreboard that
// pinned fma at ~47%.
#define TPB 192
#define MAIN_SMEM (75*16*8 + 2*CI*VP*4 + 2*KD*VP*4 + 2*CI*4)   // 63360 B

__global__ __launch_bounds__(TPB, 3) void main_kernel(
    const float* __restrict__ x,
    const float* __restrict__ A,
    const float* __restrict__ W,
    const float* __restrict__ gamma,
    const float* __restrict__ beta,
    const float* __restrict__ mean,
    const float* __restrict__ var,
    float* __restrict__ out)
{
    extern __shared__ ull smem[];
    ull*   As  = smem;                       // [75][16] packed w-pairs (13..15 zero)
    float* xwf = (float*)(As + 75*16);       // [2][64][26]
    float* ysm = xwf + 2*CI*VP;              // [2][192][26]
    float* bnA = ysm + 2*KD*VP;              // [64]
    float* bnB = bnA + CI;                   // [64]

    const int tid = threadIdx.x;
    const int n   = blockIdx.x / (LT/2);
    const int m0  = (blockIdx.x % (LT/2)) * 2;

    if (tid < CI){
        float inv = gamma[tid] * rsqrtf(var[tid] + 1e-3f);
        bnA[tid] = inv;
        bnB[tid] = beta[tid] - mean[tid]*inv;
    }
    for (int i = tid; i < 75*16; i += TPB){
        int pv = i >> 4, wp = i & 15;
        ull val = 0;
        if (wp < 13){
            float a0 = A[pv*V + 2*wp];
            float a1 = (wp < 12) ? A[pv*V + 2*wp + 1] : 0.f;
            val = pack2(a0, a1);
        }
        As[i] = val;
    }
    {
        const float4* src = (const float4*)(g_xwin + (size_t)(n*LT + m0)*CI*VP);
        float4* dst = (float4*)xwf;
        for (int i = tid; i < (2*CI*VP)/4; i += TPB) dst[i] = src[i];
    }
    __syncthreads();

    // ---- phase 1: y[k,:] = sum_c xw[c,:]*W[c,k]; 4 k-rows x 7 v-pairs per thread ----
    // v-halves: vh0 -> pairs 0..6, vh1 -> pairs 6..12 (pair 6 duplicated, identical).
    // W rows prefetched 4 iterations ahead (register pipeline, MLP=4).
    {
        const int mslot = tid / 96;
        const int s     = tid - mslot*96;
        const int kg    = s >> 1;
        const int vh    = s & 1;
        const int k0    = kg * 4;
        const int voff  = vh * 6;
        const ull* xr = (const ull*)(xwf + mslot*CI*VP) + voff;
        const float* W0 = W + k0;

        ull acc[4][7];
        #pragma unroll
        for (int i = 0; i < 4; i++)
            #pragma unroll
            for (int vp = 0; vp < 7; vp++) acc[i][vp] = 0;

        float4 wa[4];
        #pragma unroll
        for (int j = 0; j < 4; j++) wa[j] = __ldg((const float4*)(W0 + j*KD));

        #pragma unroll 1
        for (int c = 0; c < CI; c += 4){
            float4 nb[4];
            const int cn = (c + 4 < CI) ? (c + 4) : 0;   // last prefetch harmless/unused
            #pragma unroll
            for (int j = 0; j < 4; j++) nb[j] = __ldg((const float4*)(W0 + (cn + j)*KD));

            #pragma unroll
            for (int j = 0; j < 4; j++){
                ull w0 = pack2(wa[j].x, wa[j].x), w1 = pack2(wa[j].y, wa[j].y);
                ull w2 = pack2(wa[j].z, wa[j].z), w3 = pack2(wa[j].w, wa[j].w);
                const ull* xc = xr + (size_t)(c + j)*13;
                #pragma unroll
                for (int vp = 0; vp < 7; vp++){
                    ull xv = xc[vp];
                    acc[0][vp] = ffma2(w0, xv, acc[0][vp]);
                    acc[1][vp] = ffma2(w1, xv, acc[1][vp]);
                    acc[2][vp] = ffma2(w2, xv, acc[2][vp]);
                    acc[3][vp] = ffma2(w3, xv, acc[3][vp]);
                }
            }
            #pragma unroll
            for (int j = 0; j < 4; j++) wa[j] = nb[j];
        }
        #pragma unroll
        for (int i = 0; i < 4; i++){
            ull* yr = (ull*)(ysm) + (size_t)(mslot*KD + k0 + i)*13 + voff;
            #pragma unroll
            for (int vp = 0; vp < 7; vp++) yr[vp] = acc[i][vp];
        }
    }
    __syncthreads();

    // ---- phase 2: t[co,w] = sum_{p,v} y[co*3+p,v]*A[p,v,w]; 4co x 4wpairs ----
    if (tid < 128){
        const int mslot = tid >> 6;
        const int s2    = tid & 63;
        const int cog   = s2 >> 2;      // 16 groups of 4 co
        const int wg    = s2 & 3;
        const int co0   = cog * 4;

        ull tac[4][4];
        #pragma unroll
        for (int i = 0; i < 4; i++)
            #pragma unroll
            for (int j = 0; j < 4; j++) tac[i][j] = 0;

        const float* yb = ysm + (size_t)mslot*KD*VP;
        #pragma unroll
        for (int p = 0; p < 3; p++){
            const ull* Ab = As + (p*V)*16 + wg*4;
            const float* yp = yb + (size_t)(co0*3 + p)*VP;
            #pragma unroll 3
            for (int v2 = 0; v2 < 12; v2++){
                int v = 2*v2;
                ulonglong2 aA0 = *(const ulonglong2*)(Ab + (v  )*16);
                ulonglong2 aB0 = *(const ulonglong2*)(Ab + (v  )*16 + 2);
                ulonglong2 aA1 = *(const ulonglong2*)(Ab + (v+1)*16);
                ulonglong2 aB1 = *(const ulonglong2*)(Ab + (v+1)*16 + 2);
                #pragma unroll
                for (int i = 0; i < 4; i++){
                    float y0, y1;
                    unpack2(*(const ull*)(yp + i*3*VP + v), y0, y1);
                    ull yy0 = pack2(y0, y0), yy1 = pack2(y1, y1);
                    tac[i][0] = ffma2(yy0, aA0.x, tac[i][0]);
                    tac[i][1] = ffma2(yy0, aA0.y, tac[i][1]);
                    tac[i][2] = ffma2(yy0, aB0.x, tac[i][2]);
                    tac[i][3] = ffma2(yy0, aB0.y, tac[i][3]);
                    tac[i][0] = ffma2(yy1, aA1.x, tac[i][0]);
                    tac[i][1] = ffma2(yy1, aA1.y, tac[i][1]);
                    tac[i][2] = ffma2(yy1, aB1.x, tac[i][2]);
                    tac[i][3] = ffma2(yy1, aB1.y, tac[i][3]);
                }
            }
            { // leftover v = 24
                ulonglong2 aA = *(const ulonglong2*)(Ab + 24*16);
                ulonglong2 aB = *(const ulonglong2*)(Ab + 24*16 + 2);
                #pragma unroll
                for (int i = 0; i < 4; i++){
                    float yv = yp[i*3*VP + 24];
                    ull yy = pack2(yv, yv);
                    tac[i][0] = ffma2(yy, aA.x, tac[i][0]);
                    tac[i][1] = ffma2(yy, aA.y, tac[i][1]);
                    tac[i][2] = ffma2(yy, aB.x, tac[i][2]);
                    tac[i][3] = ffma2(yy, aB.y, tac[i][3]);
                }
            }
        }

        const int m = m0 + mslot;
        #pragma unroll
        for (int i = 0; i < 4; i++){
            int co = co0 + i;
            float iv = bnA[co], bb = bnB[co];
            size_t base = ((size_t)(n*CI + co)*LT + m)*V;
            #pragma unroll
            for (int j = 0; j < 4; j++){
                int w0 = 2*(wg*4 + j);
                if (w0 >= V) break;
                float t0, t1; unpack2(tac[i][j], t0, t1);
                float r0 = fmaxf(fmaf(t0, iv, bb), 0.f);
                out[base + w0] = fmaxf(r0 + x[base + w0], 0.f);
                if (w0 + 1 < V){
                    float r1 = fmaxf(fmaf(t1, iv, bb), 0.f);
                    out[base + w0 + 1] = fmaxf(r1 + x[base + w0 + 1], 0.f);
                }
            }
        }
    }
}

extern "C" void kernel_launch(void* const* d_in, const int* in_sizes, int n_in,
                              void* d_out, int out_size) {
    const float* x     = (const float*)d_in[0];
    const float* A     = (const float*)d_in[1];
    const float* W     = (const float*)d_in[2];
    const float* gamma = (const float*)d_in[3];
    const float* beta  = (const float*)d_in[4];
    const float* mean  = (const float*)d_in[5];
    const float* var   = (const float*)d_in[6];
    float* out = (float*)d_out;

    win_kernel<<<NB * 8 * 4, WTH>>>(x);

    cudaFuncSetAttribute(main_kernel, cudaFuncAttributeMaxDynamicSharedMemorySize, MAIN_SMEM);
    main_kernel<<<NB * (LT/2), TPB, MAIN_SMEM>>>(x, A, W, gamma, beta, mean, var, out);
}

// round 11
// speedup vs baseline: 3.0229x; 1.9617x over previous
#include <cuda_runtime.h>

#define NB 32
#define CI 64
#define LT 300
#define V  25
#define KD 192

typedef unsigned long long ull;
typedef unsigned int uint;

// xwin (tf32 bits), layout [n][mpair(150)][c(64)][52]  (cols 25 & 51 stay 0)
__device__ float g_xwin2[(size_t)NB * 150 * CI * 52];
// pre-swizzled W A-fragments: [Mt(12)][ks(8)][lane(32)][4] tf32 bits
__device__ __align__(16) uint g_Wfrag[12 * 8 * 32 * 4];
// A2[(p,v) padded 80][w padded 40] tf32 bits (rows>=75, cols>=25 zero)
__device__ __align__(16) uint g_A2[80 * 40];
// BN constants: [inv(64), bias(64)]
__device__ __align__(16) float g_bn[2 * CI];

__device__ __forceinline__ uint f2tf(float f){
    uint u; asm("cvt.rna.tf32.f32 %0,%1;" : "=r"(u) : "f"(f)); return u;
}
__device__ __forceinline__ ull pack2u(uint lo, uint hi){
    ull r; asm("mov.b64 %0,{%1,%2};" : "=l"(r) : "r"(lo), "r"(hi)); return r;
}
__device__ __forceinline__ void mma_tf32(float& d0, float& d1, float& d2, float& d3,
                                         uint a0, uint a1, uint a2, uint a3,
                                         uint b0, uint b1){
    asm volatile("mma.sync.aligned.m16n8k8.row.col.f32.tf32.tf32.f32 "
                 "{%0,%1,%2,%3},{%4,%5,%6,%7},{%8,%9},{%0,%1,%2,%3};"
                 : "+f"(d0), "+f"(d1), "+f"(d2), "+f"(d3)
                 : "r"(a0), "r"(a1), "r"(a2), "r"(a3), "r"(b0), "r"(b1));
}
__device__ __forceinline__ unsigned smem_u32(const void* p){
    unsigned a;
    asm("{ .reg .u64 t; cvta.to.shared.u64 t, %1; cvt.u32.u64 %0, t; }" : "=r"(a) : "l"(p));
    return a;
}

// ---------- kernel 1: window sum + one-time fragment setup (block 0) ----------
#define WCG 8
#define WLQ 75
#define WTH (WCG * V)

__global__ __launch_bounds__(WTH) void win_kernel(
    const float* __restrict__ x,
    const float* __restrict__ A,
    const float* __restrict__ W,
    const float* __restrict__ gamma,
    const float* __restrict__ beta,
    const float* __restrict__ mean,
    const float* __restrict__ var)
{
    const int b = blockIdx.x;
    const int t = threadIdx.x;

    if (b == 0){
        if (t < CI){
            float inv = gamma[t] * rsqrtf(var[t] + 1e-3f);
            g_bn[t]      = inv;
            g_bn[CI + t] = beta[t] - mean[t]*inv;
        }
        // W fragments: A1[row=k][col=c] = W[c][k]
        for (int idx = t; idx < 12*8*32*4; idx += WTH){
            int j    = idx & 3;
            int lane = (idx >> 2) & 31;
            int ks   = (idx >> 7) & 7;
            int mt   = idx >> 10;
            int r  = mt*16 + (lane >> 2) + (j & 1)*8;
            int cc = ks*8  + (lane & 3)  + (j >> 1)*4;
            g_Wfrag[idx] = f2tf(W[cc*KD + r]);
        }
        // A2[kk][w] = A[p][v][w], kk = p*25+v; pads zero
        for (int idx = t; idx < 80*40; idx += WTH){
            int r  = idx / 40;
            int wc = idx - r*40;
            uint val = 0;
            if (r < 75 && wc < V) val = f2tf(A[r*V + wc]);
            g_A2[idx] = val;
        }
    }

    const int q  = b & 3;
    const int cg = (b >> 2) & 7;
    const int n  = b >> 5;
    const int cl = t / V;
    const int v  = t - cl * V;
    const int c  = cg * WCG + cl;
    const int l0 = q * WLQ;

    const float* xp = x + ((size_t)(n * CI + c) * LT) * V + v;
    float* opb = g_xwin2 + ((size_t)n * 150 * CI + c) * 52 + v;

    float ring[9];
    #pragma unroll
    for (int j = 0; j < 9; j++) ring[j] = 0.f;
    float s = 0.f;

    #pragma unroll 1
    for (int base = 0; base < 90; base += 9) {
        #pragma unroll
        for (int j = 0; j < 9; j++) {
            int l = l0 - 8 + base + j;
            float nv = (l >= 0 && l < LT) ? xp[(size_t)l * V] : 0.f;
            s += nv - ring[j];
            ring[j] = nv;
            if (l >= l0 && l < l0 + WLQ)
                opb[(size_t)(l >> 1) * (CI*52) + (l & 1)*26] = __uint_as_float(f2tf(s));
        }
    }
}

// ---------- kernel 2: fused dual tf32 GEMM + BN + ReLU + residual ----------
// block = (n, m-pair). 256 threads (8 warps), 2 blocks/SM.
#define TPB 256
// word offsets
#define XW_OFF 0                      // [64][72]
#define YS_OFF (XW_OFF + 64*72)       // [193][68]
#define A2_OFF (YS_OFF + 193*68)      // [80][40]
#define BN_OFF (A2_OFF + 80*40)       // [128]
#define SM_WORDS (BN_OFF + 128)
#define MAIN_SMEM (SM_WORDS * 4)      // 84240 B

__global__ __launch_bounds__(TPB, 2) void main_kernel(
    const float* __restrict__ x,
    float* __restrict__ out)
{
    extern __shared__ float sm[];
    uint*  smu = (uint*)sm;

    const int tid  = threadIdx.x;
    const int wid  = tid >> 5;
    const int lane = tid & 31;
    const int lg   = lane >> 2;
    const int lq   = lane & 3;
    const int n    = blockIdx.x / 150;
    const int mp   = blockIdx.x % 150;
    const int m0   = mp * 2;

    // ---- staging ----
    {
        const unsigned sb = smem_u32(sm);
        // A2: 800 x 16B
        const char* srcA = (const char*)g_A2;
        #pragma unroll
        for (int j = 0; j < 4; j++){
            int idx = j*TPB + tid;
            if (idx < 800)
                asm volatile("cp.async.ca.shared.global [%0], [%1], 16;"
                             :: "r"(sb + A2_OFF*4 + (unsigned)(idx*16)), "l"(srcA + (size_t)idx*16));
        }
        // bn: 32 x 16B
        if (tid < 32){
            const char* srcB = (const char*)g_bn;
            asm volatile("cp.async.ca.shared.global [%0], [%1], 16;"
                         :: "r"(sb + BN_OFF*4 + (unsigned)(tid*16)), "l"(srcB + (size_t)tid*16));
        }
        // xw: 64 rows x 13 chunks of 16B; src contiguous [64][52], dst stride 72 words
        const char* srcX = (const char*)(g_xwin2 + ((size_t)n*150 + mp) * (CI*52));
        #pragma unroll
        for (int j = 0; j < 4; j++){
            int idx = j*TPB + tid;
            if (idx < 832){
                int c  = idx / 13;
                int jj = idx - c*13;
                asm volatile("cp.async.ca.shared.global [%0], [%1], 16;"
                             :: "r"(sb + (unsigned)(c*288 + jj*16)),
                                "l"(srcX + (size_t)c*208 + jj*16));
            }
        }
        asm volatile("cp.async.commit_group;");
    }
    // zero xw pad cols 52..55 and Ysm pad row 192
    if (tid < 64){
        float4 z = make_float4(0.f, 0.f, 0.f, 0.f);
        *(float4*)(sm + XW_OFF + tid*72 + 52) = z;
    } else if (tid < 132){
        sm[YS_OFF + 192*68 + (tid - 64)] = 0.f;
    }
    asm volatile("cp.async.wait_group 0;");
    __syncthreads();

    // ---- GEMM1: Y[192, 56] = W^T @ xw ; warp (mw, nw): 3 Mtiles x (4|3) Ntiles ----
    {
        const int mw = wid >> 1;
        const int nw = wid & 1;
        const int nNt = nw ? 3 : 4;
        const int ntBase = nw * 4;
        const int mtB = mw * 3;

        float acc[3][4][4];
        #pragma unroll
        for (int i = 0; i < 3; i++)
            #pragma unroll
            for (int t = 0; t < 4; t++)
                #pragma unroll
                for (int e = 0; e < 4; e++) acc[i][t][e] = 0.f;

        uint4 aC[3], aN[3];
        #pragma unroll
        for (int i = 0; i < 3; i++)
            aC[i] = *(const uint4*)(g_Wfrag + (((mtB + i)*8 + 0)*32 + lane)*4);

        #pragma unroll
        for (int ks = 0; ks < 8; ks++){
            int ksn = (ks + 1) & 7;
            #pragma unroll
            for (int i = 0; i < 3; i++)
                aN[i] = *(const uint4*)(g_Wfrag + (((mtB + i)*8 + ksn)*32 + lane)*4);

            uint b0[4], b1[4];
            #pragma unroll
            for (int t = 0; t < 4; t++){
                if (t < nNt){
                    int nt = ntBase + t;
                    b0[t] = smu[XW_OFF + (ks*8 + lq    )*72 + nt*8 + lg];
                    b1[t] = smu[XW_OFF + (ks*8 + lq + 4)*72 + nt*8 + lg];
                }
            }
            #pragma unroll
            for (int i = 0; i < 3; i++)
                #pragma unroll
                for (int t = 0; t < 4; t++)
                    if (t < nNt)
                        mma_tf32(acc[i][t][0], acc[i][t][1], acc[i][t][2], acc[i][t][3],
                                 aC[i].x, aC[i].y, aC[i].z, aC[i].w, b0[t], b1[t]);
            #pragma unroll
            for (int i = 0; i < 3; i++) aC[i] = aN[i];
        }

        // write Y to smem as tf32 (rows k = co*3+p, cols m*26+v)
        #pragma unroll
        for (int i = 0; i < 3; i++)
            #pragma unroll
            for (int t = 0; t < 4; t++)
                if (t < nNt){
                    int nt = ntBase + t;
                    int row0 = (mtB + i)*16 + lg;
                    int col0 = nt*8 + 2*lq;
                    *(ull*)(sm + YS_OFF + row0*68 + col0) =
                        pack2u(f2tf(acc[i][t][0]), f2tf(acc[i][t][1]));
                    *(ull*)(sm + YS_OFF + (row0 + 8)*68 + col0) =
                        pack2u(f2tf(acc[i][t][2]), f2tf(acc[i][t][3]));
                }
    }
    __syncthreads();

    // ---- GEMM2: T[(co,m)=128, 32] = Yr[128, 80] @ A2[80, 32]; warp = Mtile ----
    {
        float acc2[4][4];
        #pragma unroll
        for (int t = 0; t < 4; t++)
            #pragma unroll
            for (int e = 0; e < 4; e++) acc2[t][e] = 0.f;

        const int R    = wid*16 + lg;     // row of a0/a2
        const int coA  = R >> 1;
        const int colm = (R & 1) * 26;

        #pragma unroll
        for (int ks = 0; ks < 10; ks++){
            int C0 = ks*8 + lq;
            int C1 = C0 + 4;
            int p0 = (41*C0) >> 10;  int v0 = C0 - 25*p0;
            int p1 = (41*C1) >> 10;  int v1 = C1 - 25*p1;

            uint a0 = smu[YS_OFF + ( coA     *3 + p0)*68 + colm + v0];
            uint a1 = smu[YS_OFF + ((coA + 4)*3 + p0)*68 + colm + v0];
            uint a2 = smu[YS_OFF + ( coA     *3 + p1)*68 + colm + v1];
            uint a3 = smu[YS_OFF + ((coA + 4)*3 + p1)*68 + colm + v1];

            #pragma unroll
            for (int t = 0; t < 4; t++){
                uint b0 = smu[A2_OFF + C0*40 + t*8 + lg];
                uint b1 = smu[A2_OFF + C1*40 + t*8 + lg];
                mma_tf32(acc2[t][0], acc2[t][1], acc2[t][2], acc2[t][3],
                         a0, a1, a2, a3, b0, b1);
            }
        }

        // epilogue: BN + ReLU + residual + ReLU
        #pragma unroll
        for (int t = 0; t < 4; t++){
            int wc = t*8 + 2*lq;
            #pragma unroll
            for (int j = 0; j < 2; j++){
                int Rr = wid*16 + lg + 8*j;
                int co = Rr >> 1;
                int m2 = m0 + (Rr & 1);
                float d0 = acc2[t][2*j];
                float d1 = acc2[t][2*j + 1];
                float iv = sm[BN_OFF + co];
                float bb = sm[BN_OFF + 64 + co];
                size_t base = ((size_t)(n*CI + co)*LT + m2)*V;
                if (wc < V){
                    float r0 = fmaxf(fmaf(d0, iv, bb), 0.f);
                    out[base + wc] = fmaxf(r0 + x[base + wc], 0.f);
                }
                if (wc + 1 < V){
                    float r1 = fmaxf(fmaf(d1, iv, bb), 0.f);
                    out[base + wc + 1] = fmaxf(r1 + x[base + wc + 1], 0.f);
                }
            }
        }
    }
}

extern "C" void kernel_launch(void* const* d_in, const int* in_sizes, int n_in,
                              void* d_out, int out_size) {
    const float* x     = (const float*)d_in[0];
    const float* A     = (const float*)d_in[1];
    const float* W     = (const float*)d_in[2];
    const float* gamma = (const float*)d_in[3];
    const float* beta  = (const float*)d_in[4];
    const float* mean  = (const float*)d_in[5];
    const float* var   = (const float*)d_in[6];
    float* out = (float*)d_out;

    win_kernel<<<NB * 8 * 4, WTH>>>(x, A, W, gamma, beta, mean, var);

    cudaFuncSetAttribute(main_kernel, cudaFuncAttributeMaxDynamicSharedMemorySize, MAIN_SMEM);
    main_kernel<<<NB * 150, TPB, MAIN_SMEM>>>(x, out);
}

// round 12
// speedup vs baseline: 3.1510x; 1.0424x over previous
#include <cuda_runtime.h>

#define NB 32
#define CI 64
#define LT 300
#define V  25
#define KD 192

typedef unsigned long long ull;
typedef unsigned int uint;

// xwin (tf32 bits), layout [n][mpair(150)][c(64)][52]  (cols 25 & 51 stay 0)
__device__ float g_xwin2[(size_t)NB * 150 * CI * 52];
// pre-swizzled W A-fragments: [Mt(12)][ks(8)][lane(32)][4] tf32 bits
__device__ __align__(16) uint g_Wfrag[12 * 8 * 32 * 4];
// pre-swizzled GEMM2 B-fragments: [ks(10)][t(4)][lane(32)] -> (b0,b1) tf32 bits
__device__ __align__(16) ull  g_A2frag[10 * 4 * 32];
// BN constants: [inv(64), bias(64)]
__device__ __align__(16) float g_bn[2 * CI];

__device__ __forceinline__ uint f2tf(float f){
    uint u; asm("cvt.rna.tf32.f32 %0,%1;" : "=r"(u) : "f"(f)); return u;
}
__device__ __forceinline__ ull pack2u(uint lo, uint hi){
    ull r; asm("mov.b64 %0,{%1,%2};" : "=l"(r) : "r"(lo), "r"(hi)); return r;
}
__device__ __forceinline__ void unpack2u(ull v, uint& lo, uint& hi){
    asm("mov.b64 {%0,%1},%2;" : "=r"(lo), "=r"(hi) : "l"(v));
}
__device__ __forceinline__ void mma_tf32(float& d0, float& d1, float& d2, float& d3,
                                         uint a0, uint a1, uint a2, uint a3,
                                         uint b0, uint b1){
    asm volatile("mma.sync.aligned.m16n8k8.row.col.f32.tf32.tf32.f32 "
                 "{%0,%1,%2,%3},{%4,%5,%6,%7},{%8,%9},{%0,%1,%2,%3};"
                 : "+f"(d0), "+f"(d1), "+f"(d2), "+f"(d3)
                 : "r"(a0), "r"(a1), "r"(a2), "r"(a3), "r"(b0), "r"(b1));
}
__device__ __forceinline__ unsigned smem_u32(const void* p){
    unsigned a;
    asm("{ .reg .u64 t; cvta.to.shared.u64 t, %1; cvt.u32.u64 %0, t; }" : "=r"(a) : "l"(p));
    return a;
}

// ---------- kernel 1: window sum + one-time fragment setup (block 0) ----------
#define WCG 8
#define WLQ 75
#define WTH (WCG * V)

__global__ __launch_bounds__(WTH) void win_kernel(
    const float* __restrict__ x,
    const float* __restrict__ A,
    const float* __restrict__ W,
    const float* __restrict__ gamma,
    const float* __restrict__ beta,
    const float* __restrict__ mean,
    const float* __restrict__ var)
{
    const int b = blockIdx.x;
    const int t = threadIdx.x;

    if (b == 0){
        if (t < CI){
            float inv = gamma[t] * rsqrtf(var[t] + 1e-3f);
            g_bn[t]      = inv;
            g_bn[CI + t] = beta[t] - mean[t]*inv;
        }
        // W fragments: A1[row=k][col=c] = W[c][k]
        for (int idx = t; idx < 12*8*32*4; idx += WTH){
            int j    = idx & 3;
            int lane = (idx >> 2) & 31;
            int ks   = (idx >> 7) & 7;
            int mt   = idx >> 10;
            int r  = mt*16 + (lane >> 2) + (j & 1)*8;
            int cc = ks*8  + (lane & 3)  + (j >> 1)*4;
            g_Wfrag[idx] = f2tf(W[cc*KD + r]);
        }
        // GEMM2 B fragments over padded K: C in [0,80), row C -> (p=C/26, v=C%26)
        // zero when v==25 or C>=78 or w>=25.
        for (int idx = t; idx < 10*4*32; idx += WTH){
            int lane = idx & 31;
            int tt   = (idx >> 5) & 3;
            int ks   = idx >> 7;
            int lq = lane & 3, lg = lane >> 2;
            int C0 = ks*8 + lq, C1 = C0 + 4;
            int wc = tt*8 + lg;
            uint b0 = 0, b1 = 0;
            if (wc < V){
                int p0 = C0/26, v0 = C0 - 26*p0;
                if (C0 < 78 && v0 < V) b0 = f2tf(A[(p0*V + v0)*V + wc]);
                int p1 = C1/26, v1 = C1 - 26*p1;
                if (C1 < 78 && v1 < V) b1 = f2tf(A[(p1*V + v1)*V + wc]);
            }
            g_A2frag[idx] = pack2u(b0, b1);
        }
    }

    const int q  = b & 3;
    const int cg = (b >> 2) & 7;
    const int n  = b >> 5;
    const int cl = t / V;
    const int v  = t - cl * V;
    const int c  = cg * WCG + cl;
    const int l0 = q * WLQ;

    const float* xp = x + ((size_t)(n * CI + c) * LT) * V + v;
    float* opb = g_xwin2 + ((size_t)n * 150 * CI + c) * 52 + v;

    float ring[9];
    #pragma unroll
    for (int j = 0; j < 9; j++) ring[j] = 0.f;
    float s = 0.f;

    #pragma unroll 1
    for (int base = 0; base < 90; base += 9) {
        #pragma unroll
        for (int j = 0; j < 9; j++) {
            int l = l0 - 8 + base + j;
            float nv = (l >= 0 && l < LT) ? xp[(size_t)l * V] : 0.f;
            s += nv - ring[j];
            ring[j] = nv;
            if (l >= l0 && l < l0 + WLQ)
                opb[(size_t)(l >> 1) * (CI*52) + (l & 1)*26] = __uint_as_float(f2tf(s));
        }
    }
}

// ---------- kernel 2: fused dual tf32 GEMM + BN + ReLU + residual ----------
// block = (n, m-pair). 256 threads (8 warps), 2 blocks/SM.
// smem: xw [64][72] | Yr [128][84]  (Yr holds GEMM1 output pre-swizzled into
// GEMM2's A-fragment layout: row = co*2+m, col = p*26+v, K padded to 80)
#define TPB 256
#define XW_OFF 0
#define YR_OFF (XW_OFF + 64*72)
#define SM_WORDS (YR_OFF + 128*84)
#define MAIN_SMEM (SM_WORDS * 4)      // 61440 B

__global__ __launch_bounds__(TPB, 2) void main_kernel(
    const float* __restrict__ x,
    float* __restrict__ out)
{
    extern __shared__ float sm[];
    uint*  smu = (uint*)sm;

    const int tid  = threadIdx.x;
    const int wid  = tid >> 5;
    const int lane = tid & 31;
    const int lg   = lane >> 2;
    const int lq   = lane & 3;
    const int n    = blockIdx.x / 150;
    const int mp   = blockIdx.x % 150;
    const int m0   = mp * 2;

    // ---- staging: only xw (13.3 KB) ----
    {
        const unsigned sb = smem_u32(sm);
        const char* srcX = (const char*)(g_xwin2 + ((size_t)n*150 + mp) * (CI*52));
        #pragma unroll
        for (int j = 0; j < 4; j++){
            int idx = j*TPB + tid;
            if (idx < 832){
                int c  = idx / 13;
                int jj = idx - c*13;
                asm volatile("cp.async.ca.shared.global [%0], [%1], 16;"
                             :: "r"(sb + (unsigned)(c*288 + jj*16)),
                                "l"(srcX + (size_t)c*208 + jj*16));
            }
        }
        asm volatile("cp.async.commit_group;");
    }
    // zero xw pad cols 52..55 and Yr pad cols 78..79
    if (tid < 64){
        float4 z = make_float4(0.f, 0.f, 0.f, 0.f);
        *(float4*)(sm + XW_OFF + tid*72 + 52) = z;
    }
    sm[YR_OFF + (tid >> 1)*84 + 78 + (tid & 1)] = 0.f;
    asm volatile("cp.async.wait_group 0;");
    __syncthreads();

    // ---- GEMM1: Y[192, 56] = W^T @ xw ; warp (mw, nw): 3 Mtiles x (4|3) Ntiles ----
    {
        const int mw = wid >> 1;
        const int nw = wid & 1;
        const int nNt = nw ? 3 : 4;
        const int ntBase = nw * 4;
        const int mtB = mw * 3;

        float acc[3][4][4];
        #pragma unroll
        for (int i = 0; i < 3; i++)
            #pragma unroll
            for (int t = 0; t < 4; t++)
                #pragma unroll
                for (int e = 0; e < 4; e++) acc[i][t][e] = 0.f;

        uint4 aC[3], aN[3];
        #pragma unroll
        for (int i = 0; i < 3; i++)
            aC[i] = *(const uint4*)(g_Wfrag + (((mtB + i)*8 + 0)*32 + lane)*4);

        #pragma unroll
        for (int ks = 0; ks < 8; ks++){
            int ksn = (ks + 1) & 7;
            #pragma unroll
            for (int i = 0; i < 3; i++)
                aN[i] = *(const uint4*)(g_Wfrag + (((mtB + i)*8 + ksn)*32 + lane)*4);

            uint b0[4], b1[4];
            #pragma unroll
            for (int t = 0; t < 4; t++){
                if (t < nNt){
                    int nt = ntBase + t;
                    b0[t] = smu[XW_OFF + (ks*8 + lq    )*72 + nt*8 + lg];
                    b1[t] = smu[XW_OFF + (ks*8 + lq + 4)*72 + nt*8 + lg];
                }
            }
            #pragma unroll
            for (int i = 0; i < 3; i++)
                #pragma unroll
                for (int t = 0; t < 4; t++)
                    if (t < nNt)
                        mma_tf32(acc[i][t][0], acc[i][t][1], acc[i][t][2], acc[i][t][3],
                                 aC[i].x, aC[i].y, aC[i].z, aC[i].w, b0[t], b1[t]);
            #pragma unroll
            for (int i = 0; i < 3; i++) aC[i] = aN[i];
        }

        // scatter Y into GEMM2 A-fragment layout: row = co*2+m, col = p*26+v.
        // (v,v+1) pairs stay inside one 26-wide p-block -> aligned 8B stores;
        // v==25 slots receive exact zeros (xw pad col is zero).
        #pragma unroll
        for (int i = 0; i < 3; i++){
            int k1  = (mtB + i)*16 + lg;
            int co1 = k1/3,  pp1 = k1 - co1*3;
            int k2  = k1 + 8;
            int co2 = k2/3,  pp2 = k2 - co2*3;
            #pragma unroll
            for (int t = 0; t < 4; t++)
                if (t < nNt){
                    int col0 = (ntBase + t)*8 + 2*lq;
                    if (col0 < 52){
                        int m  = (col0 >= 26) ? 1 : 0;
                        int v  = col0 - 26*m;
                        *(ull*)(sm + YR_OFF + (co1*2 + m)*84 + pp1*26 + v) =
                            pack2u(f2tf(acc[i][t][0]), f2tf(acc[i][t][1]));
                        *(ull*)(sm + YR_OFF + (co2*2 + m)*84 + pp2*26 + v) =
                            pack2u(f2tf(acc[i][t][2]), f2tf(acc[i][t][3]));
                    }
                }
        }
    }
    __syncthreads();

    // ---- GEMM2: T[128, 32] = Yr[128, 80] @ A2pad[80, 32]; warp = Mtile ----
    {
        float acc2[4][4];
        #pragma unroll
        for (int t = 0; t < 4; t++)
            #pragma unroll
            for (int e = 0; e < 4; e++) acc2[t][e] = 0.f;

        const int R = wid*16 + lg;
        const uint* yr = smu + YR_OFF;

        ull bcur[4];
        #pragma unroll
        for (int t = 0; t < 4; t++) bcur[t] = g_A2frag[t*32 + lane];

        #pragma unroll
        for (int ks = 0; ks < 10; ks++){
            int ksn = (ks + 1 < 10) ? ks + 1 : 0;
            ull bnx[4];
            #pragma unroll
            for (int t = 0; t < 4; t++) bnx[t] = g_A2frag[(ksn*4 + t)*32 + lane];

            int C0 = ks*8 + lq;
            int C1 = C0 + 4;
            uint a0 = yr[ R     *84 + C0];
            uint a1 = yr[(R + 8)*84 + C0];
            uint a2 = yr[ R     *84 + C1];
            uint a3 = yr[(R + 8)*84 + C1];

            #pragma unroll
            for (int t = 0; t < 4; t++){
                uint b0, b1; unpack2u(bcur[t], b0, b1);
                mma_tf32(acc2[t][0], acc2[t][1], acc2[t][2], acc2[t][3],
                         a0, a1, a2, a3, b0, b1);
            }
            #pragma unroll
            for (int t = 0; t < 4; t++) bcur[t] = bnx[t];
        }

        // epilogue: BN + ReLU + residual + ReLU
        #pragma unroll
        for (int t = 0; t < 4; t++){
            int wc = t*8 + 2*lq;
            #pragma unroll
            for (int j = 0; j < 2; j++){
                int Rr = wid*16 + lg + 8*j;
                int co = Rr >> 1;
                int m2 = m0 + (Rr & 1);
                float d0 = acc2[t][2*j];
                float d1 = acc2[t][2*j + 1];
                float iv = __ldg(g_bn + co);
                float bb = __ldg(g_bn + 64 + co);
                size_t base = ((size_t)(n*CI + co)*LT + m2)*V;
                if (wc < V){
                    float r0 = fmaxf(fmaf(d0, iv, bb), 0.f);
                    out[base + wc] = fmaxf(r0 + x[base + wc], 0.f);
                }
                if (wc + 1 < V){
                    float r1 = fmaxf(fmaf(d1, iv, bb), 0.f);
                    out[base + wc + 1] = fmaxf(r1 + x[base + wc + 1], 0.f);
                }
            }
        }
    }
}

extern "C" void kernel_launch(void* const* d_in, const int* in_sizes, int n_in,
                              void* d_out, int out_size) {
    const float* x     = (const float*)d_in[0];
    const float* A     = (const float*)d_in[1];
    const float* W     = (const float*)d_in[2];
    const float* gamma = (const float*)d_in[3];
    const float* beta  = (const float*)d_in[4];
    const float* mean  = (const float*)d_in[5];
    const float* var   = (const float*)d_in[6];
    float* out = (float*)d_out;

    win_kernel<<<NB * 8 * 4, WTH>>>(x, A, W, gamma, beta, mean, var);

    cudaFuncSetAttribute(main_kernel, cudaFuncAttributeMaxDynamicSharedMemorySize, MAIN_SMEM);
    main_kernel<<<NB * 150, TPB, MAIN_SMEM>>>(x, out);
}